// round 4
// baseline (speedup 1.0000x reference)
#include <cuda_runtime.h>

// embedding_pooling: out[b, (c-1)*256 + d] = relu(max_{l: label[b,l]==c} x[b,l,d]), empty->0
//  - relu + empty-case == fmax chain initialized at 0.
//  - Labels are int32 on device (JAX x64 disabled; proven by R2/R3 benches).
//
// One block per batch row b (256 blocks, 512 threads, 2 CTAs/SM -> single wave).
// Each block sweeps its 512KB x-segment once, ascending, skipping label-0 rows.
// 8 teams of 64 threads; team handles rows j == team (mod 8); lane owns one
// float4 column. Per-row class is team-uniform -> uniform branch into one of 5
// register accumulators (1 predicated LDG.128 + 4 FMNMX per float4).

#define BATCH 256
#define LSEQ  512
#define DDIM  256
#define NC    5

#define FM4(a, v)  { a.x = fmaxf(a.x, v.x); a.y = fmaxf(a.y, v.y); \
                     a.z = fmaxf(a.z, v.z); a.w = fmaxf(a.w, v.w); }

#define ACC(c, v)  { if (c == 1)      FM4(a1, v) \
                     else if (c == 2) FM4(a2, v) \
                     else if (c == 3) FM4(a3, v) \
                     else if (c == 4) FM4(a4, v) \
                     else if (c == 5) FM4(a5, v) }

__global__ __launch_bounds__(512, 2)
void embedding_pooling_kernel(const float* __restrict__ x,
                              const int* __restrict__ labels,
                              float* __restrict__ out)
{
    __shared__ int    s_cls[LSEQ];
    __shared__ float4 s_red[8][NC][64];   // 40 KB

    const int tid = threadIdx.x;
    const int b   = blockIdx.x;

    // ---- Phase 1: stage this row's 512 labels (coalesced 2KB read).
    s_cls[tid] = labels[(size_t)b * LSEQ + tid];
    __syncthreads();

    // ---- Phase 2: single ascending sweep, 4 rows per iteration for MLP.
    const int team = tid >> 6;     // 0..7
    const int col  = tid & 63;     // float4 column
    const float4* __restrict__ X4 = (const float4*)x + (size_t)b * LSEQ * (DDIM / 4);

    float4 a1 = make_float4(0.f, 0.f, 0.f, 0.f);
    float4 a2 = a1, a3 = a1, a4 = a1, a5 = a1;

    for (int j = team; j < LSEQ; j += 32) {
        const int c0 = s_cls[j];
        const int c1 = s_cls[j +  8];
        const int c2 = s_cls[j + 16];
        const int c3 = s_cls[j + 24];
        float4 v0, v1, v2, v3;
        if (c0) v0 = X4[(size_t)(j     ) * (DDIM / 4) + col];
        if (c1) v1 = X4[(size_t)(j +  8) * (DDIM / 4) + col];
        if (c2) v2 = X4[(size_t)(j + 16) * (DDIM / 4) + col];
        if (c3) v3 = X4[(size_t)(j + 24) * (DDIM / 4) + col];
        ACC(c0, v0);
        ACC(c1, v1);
        ACC(c2, v2);
        ACC(c3, v3);
    }

    s_red[team][0][col] = a1;
    s_red[team][1][col] = a2;
    s_red[team][2][col] = a3;
    s_red[team][3][col] = a4;
    s_red[team][4][col] = a5;
    __syncthreads();

    // ---- Phase 3: fold 8 teams; one float4 store per output group.
    if (tid < NC * 64) {
        const int cls = tid >> 6;
        const int cc  = tid & 63;
        float4 m = s_red[0][cls][cc];
#pragma unroll
        for (int g = 1; g < 8; g++) {
            const float4 v = s_red[g][cls][cc];
            FM4(m, v);
        }
        float4* O4 = (float4*)out;
        O4[(size_t)b * (NC * (DDIM / 4)) + tid] = m;
    }
}

extern "C" void kernel_launch(void* const* d_in, const int* in_sizes, int n_in,
                              void* d_out, int out_size)
{
    const float* x      = (const float*)d_in[0];
    const int*   labels = (const int*)d_in[1];
    float*       out    = (float*)d_out;

    embedding_pooling_kernel<<<BATCH, 512>>>(x, labels, out);
}

// round 6
// speedup vs baseline: 1.0846x; 1.0846x over previous
#include <cuda_runtime.h>

// embedding_pooling: out[b, (c-1)*256 + d] = relu(max_{l: label[b,l]==c} x[b,l,d]), empty->0
//  - relu + empty-case == fmax chain initialized at 0.
//  - Labels are int32 on device (JAX x64 disabled; proven by R2 fail / R3 pass).
//
// One block per (b, class) = 1280 CTAs x 256 threads (32 regs -> 8 CTAs/SM,
// near-single-wave). Phase 1 compacts matching l-indices in ASCENDING order via
// warp ballots (no shared atomics). Phase 2 streams the gathered ~85 rows with
// 2 x LDG.128 + 8 FMNMX per row per thread-pair of columns.

#define BATCH 256
#define LSEQ  512
#define DDIM  256
#define NC    5

__global__ __launch_bounds__(256, 8)
void embedding_pooling_kernel(const float* __restrict__ x,
                              const int* __restrict__ labels,
                              float* __restrict__ out)
{
    __shared__ int    s_idx[LSEQ];
    __shared__ int    s_base[17];     // exclusive scan of 16 warp-chunk counts
    __shared__ float4 s_red[8][64];

    const int tid  = threadIdx.x;
    const int w    = tid >> 5;
    const int lane = tid & 31;
    const int b    = blockIdx.x / NC;
    const int c    = (blockIdx.x % NC) + 1;

    // ---- Phase 1: ordered compaction of l with label == c.
    // 512 labels = 16 warp-chunks in ascending l order: chunk = k*8 + w, k in {0,1}.
    const int* lab_row = labels + (size_t)b * LSEQ;
    const int l0 = tid;
    const int l1 = tid + 256;
    const bool f0 = (lab_row[l0] == c);
    const bool f1 = (lab_row[l1] == c);
    const unsigned m0 = __ballot_sync(0xffffffffu, f0);
    const unsigned m1 = __ballot_sync(0xffffffffu, f1);
    if (lane == 0) {
        s_base[w]     = __popc(m0);   // counts parked in s_base, scanned below
        s_base[8 + w] = __popc(m1);
    }
    __syncthreads();
    if (tid == 0) {
        int acc = 0;
#pragma unroll
        for (int i = 0; i < 16; i++) {
            const int t = s_base[i];
            s_base[i] = acc;
            acc += t;
        }
        s_base[16] = acc;
    }
    __syncthreads();
    const unsigned below = (1u << lane) - 1u;
    if (f0) s_idx[s_base[w]     + __popc(m0 & below)] = l0;
    if (f1) s_idx[s_base[8 + w] + __popc(m1 & below)] = l1;
    __syncthreads();
    const int n = s_base[16];

    // ---- Phase 2: warp-strided max over gathered rows (ascending order).
    // Lane q owns float4 columns q (d in [0,128)) and 32+q (d in [128,256)).
    const int q = tid & 31;
    const float4* X4 = (const float4*)x;
    const int base_row = b * LSEQ;

    float4 m0v = make_float4(0.f, 0.f, 0.f, 0.f);
    float4 m1v = make_float4(0.f, 0.f, 0.f, 0.f);

#pragma unroll 2
    for (int j = w; j < n; j += 8) {
        const int l = s_idx[j];
        const float4* row = X4 + (size_t)(base_row + l) * (DDIM / 4);
        const float4 v0 = row[q];
        const float4 v1 = row[32 + q];
        m0v.x = fmaxf(m0v.x, v0.x); m0v.y = fmaxf(m0v.y, v0.y);
        m0v.z = fmaxf(m0v.z, v0.z); m0v.w = fmaxf(m0v.w, v0.w);
        m1v.x = fmaxf(m1v.x, v1.x); m1v.y = fmaxf(m1v.y, v1.y);
        m1v.z = fmaxf(m1v.z, v1.z); m1v.w = fmaxf(m1v.w, v1.w);
    }

    s_red[w][q]      = m0v;
    s_red[w][32 + q] = m1v;
    __syncthreads();

    // ---- Phase 3: fold 8 warps; one float4 store per column.
    if (tid < 64) {
        float4 m = s_red[0][tid];
#pragma unroll
        for (int g = 1; g < 8; g++) {
            const float4 v = s_red[g][tid];
            m.x = fmaxf(m.x, v.x); m.y = fmaxf(m.y, v.y);
            m.z = fmaxf(m.z, v.z); m.w = fmaxf(m.w, v.w);
        }
        float4* O4 = (float4*)out;
        O4[(size_t)b * (NC * (DDIM / 4)) + (size_t)(c - 1) * (DDIM / 4) + tid] = m;
    }
}

extern "C" void kernel_launch(void* const* d_in, const int* in_sizes, int n_in,
                              void* d_out, int out_size)
{
    const float* x      = (const float*)d_in[0];
    const int*   labels = (const int*)d_in[1];
    float*       out    = (float*)d_out;

    embedding_pooling_kernel<<<BATCH * NC, 256>>>(x, labels, out);
}

// round 7
// speedup vs baseline: 1.0908x; 1.0057x over previous
#include <cuda_runtime.h>

// embedding_pooling: out[b, (c-1)*256 + d] = relu(max_{l: label[b,l]==c} x[b,l,d]), empty->0
//  - relu + empty-case == fmax chain initialized at 0.
//  - Labels are int32 on device (proven R2 fail / R3 pass).
//
// One CTA per (b, class) = 1280 CTAs, but only 128 threads (4 warps) each so
// ALL 1280 CTAs are resident in a single wave (>=12 CTAs/SM at 32 regs):
// removes the 96-CTA second-wave tail that capped DRAM at ~59%.
// Phase 1: ballot-based ordered compaction of matching l's.
// Phase 2: warp-strided stream, 2 x LDG.128 + 8 FMNMX per row per thread.

#define BATCH 256
#define LSEQ  512
#define DDIM  256
#define NC    5
#define NW    4      // warps per CTA

__global__ __launch_bounds__(128, 12)
void embedding_pooling_kernel(const float* __restrict__ x,
                              const int* __restrict__ labels,
                              float* __restrict__ out)
{
    __shared__ int    s_idx[LSEQ];
    __shared__ int    s_base[17];      // exclusive scan of 16 warp-chunk counts
    __shared__ float4 s_red[NW][64];

    const int tid  = threadIdx.x;
    const int w    = tid >> 5;         // 0..3
    const int lane = tid & 31;
    const int b    = blockIdx.x / NC;
    const int c    = (blockIdx.x % NC) + 1;

    // ---- Phase 1: ordered compaction of l with label == c.
    // 512 labels = 16 chunks of 32, ascending order: chunk = k*NW + w, k=0..3.
    const int* lab_row = labels + (size_t)b * LSEQ;
    bool     f[4];
    unsigned m[4];
#pragma unroll
    for (int k = 0; k < 4; k++) {
        f[k] = (lab_row[tid + 128 * k] == c);
        m[k] = __ballot_sync(0xffffffffu, f[k]);
    }
    if (lane == 0) {
#pragma unroll
        for (int k = 0; k < 4; k++)
            s_base[k * NW + w] = __popc(m[k]);
    }
    __syncthreads();
    if (tid == 0) {
        int acc = 0;
#pragma unroll
        for (int i = 0; i < 16; i++) {
            const int t = s_base[i];
            s_base[i] = acc;
            acc += t;
        }
        s_base[16] = acc;
    }
    __syncthreads();
    const unsigned below = (1u << lane) - 1u;
#pragma unroll
    for (int k = 0; k < 4; k++)
        if (f[k]) s_idx[s_base[k * NW + w] + __popc(m[k] & below)] = tid + 128 * k;
    __syncthreads();
    const int n = s_base[16];

    // ---- Phase 2: warp-strided max over gathered rows (ascending order).
    // Lane q owns float4 columns q (d in [0,128)) and 32+q (d in [128,256)).
    const int q = lane;
    const float4* X4 = (const float4*)x;
    const int base_row = b * LSEQ;

    float4 m0v = make_float4(0.f, 0.f, 0.f, 0.f);
    float4 m1v = make_float4(0.f, 0.f, 0.f, 0.f);

#pragma unroll 2
    for (int j = w; j < n; j += NW) {
        const int l = s_idx[j];
        const float4* row = X4 + (size_t)(base_row + l) * (DDIM / 4);
        const float4 v0 = row[q];
        const float4 v1 = row[32 + q];
        m0v.x = fmaxf(m0v.x, v0.x); m0v.y = fmaxf(m0v.y, v0.y);
        m0v.z = fmaxf(m0v.z, v0.z); m0v.w = fmaxf(m0v.w, v0.w);
        m1v.x = fmaxf(m1v.x, v1.x); m1v.y = fmaxf(m1v.y, v1.y);
        m1v.z = fmaxf(m1v.z, v1.z); m1v.w = fmaxf(m1v.w, v1.w);
    }

    s_red[w][q]      = m0v;
    s_red[w][32 + q] = m1v;
    __syncthreads();

    // ---- Phase 3: fold 4 warps; one float4 store per column.
    if (tid < 64) {
        float4 mm = s_red[0][tid];
#pragma unroll
        for (int g = 1; g < NW; g++) {
            const float4 v = s_red[g][tid];
            mm.x = fmaxf(mm.x, v.x); mm.y = fmaxf(mm.y, v.y);
            mm.z = fmaxf(mm.z, v.z); mm.w = fmaxf(mm.w, v.w);
        }
        float4* O4 = (float4*)out;
        O4[(size_t)b * (NC * (DDIM / 4)) + (size_t)(c - 1) * (DDIM / 4) + tid] = mm;
    }
}

extern "C" void kernel_launch(void* const* d_in, const int* in_sizes, int n_in,
                              void* d_out, int out_size)
{
    const float* x      = (const float*)d_in[0];
    const int*   labels = (const int*)d_in[1];
    float*       out    = (float*)d_out;

    embedding_pooling_kernel<<<BATCH * NC, 128>>>(x, labels, out);
}